// round 14
// baseline (speedup 1.0000x reference)
#include <cuda_runtime.h>
#include <cuda_fp16.h>
#include <cstdint>
#include <cstddef>

// INT4 packed linear: y[64, 28672] = x[64, 8192] @ dequant(w_packed, scales) + bias
// Harness canonicalizes fp16 tensors to float32 (lossless): x/scales/bias/out are f32.
// Math replicates reference: fp16 dequant ((nib-8)*s in fp16), fp32 MMA accum,
// fp16 rounding of y, fp16 bias add, upcast to f32 for the store.
//
// R12: M-split CTAs (M32 x N64), 896 CTAs, 36KB static SMEM, occupancy 6
//      (24 warps/SM). Halves LDSM redundancy + doubles latency hiding.
//      No partials/finalize (disjoint outputs). mh is fast grid dim -> sibling
//      CTAs share w tiles through L2.

#define K_DIM   8192
#define N_DIM   28672
#define M_DIM   64
#define BM      32            // rows per CTA
#define BN      64            // columns per CTA (4 warps x 16 cols)
#define BK      64            // k per stage (32 packed rows); scale-group = 2 stages
#define NSTAGE  (K_DIM / BK)  // 128 stages
#define NBUF    3
#define XS_ELEMS (BM * BK)        // 2048 halves = 4KB / buffer
#define WS_ELEMS ((BK / 2) * BN)  // 2048 ints  = 8KB / buffer

// fp16 copy of x (scratch via __device__ global)
__device__ __align__(16) __half g_xh[M_DIM * K_DIM];

__global__ void convert_x_kernel(const float* __restrict__ xf) {
    int i = (blockIdx.x * blockDim.x + threadIdx.x) * 4;
    float4 v = *reinterpret_cast<const float4*>(xf + i);
    *reinterpret_cast<__half2*>(&g_xh[i])     = __floats2half2_rn(v.x, v.y);
    *reinterpret_cast<__half2*>(&g_xh[i + 2]) = __floats2half2_rn(v.z, v.w);
}

__device__ __forceinline__ unsigned smem_u32(const void* p) {
    return (unsigned)__cvta_generic_to_shared(p);
}

__device__ __forceinline__ void ldsm_x4(unsigned& r0, unsigned& r1, unsigned& r2, unsigned& r3,
                                        unsigned addr) {
    asm volatile("ldmatrix.sync.aligned.m8n8.x4.shared.b16 {%0,%1,%2,%3}, [%4];\n"
                 : "=r"(r0), "=r"(r1), "=r"(r2), "=r"(r3)
                 : "r"(addr));
}

__device__ __forceinline__ void mma_16816(float& c0, float& c1, float& c2, float& c3,
                                          unsigned a0, unsigned a1, unsigned a2, unsigned a3,
                                          unsigned b0, unsigned b1) {
    asm volatile("mma.sync.aligned.m16n8k16.row.col.f32.f16.f16.f32 "
                 "{%0,%1,%2,%3}, {%4,%5,%6,%7}, {%8,%9}, {%0,%1,%2,%3};\n"
                 : "+f"(c0), "+f"(c1), "+f"(c2), "+f"(c3)
                 : "r"(a0), "r"(a1), "r"(a2), "r"(a3), "r"(b0), "r"(b1));
}

__device__ __forceinline__ void cp_async16(unsigned saddr, const void* gaddr) {
    asm volatile("cp.async.cg.shared.global [%0], [%1], 16;\n"
                 :: "r"(saddr), "l"(gaddr));
}

// q in [0,256): fp16x2 {1024+lo, 1024+hi} - 1032 (exact), * scale (one fp16 rounding).
__device__ __forceinline__ unsigned dequant(unsigned q, __half2 s2) {
    unsigned t = ((q | (q << 12)) | 0x64006400u) & 0x640F640Fu;
    __half2 th = *reinterpret_cast<__half2*>(&t);
    const unsigned offc = 0x64086408u;  // half2 {1032, 1032}
    __half2 off = *reinterpret_cast<const __half2*>(&offc);
    __half2 wv = __hmul2(__hsub2(th, off), s2);
    return *reinterpret_cast<unsigned*>(&wv);
}

__global__ __launch_bounds__(128, 6)
void int4_linear_kernel(const int* __restrict__ w,
                        const float* __restrict__ scales,
                        const float* __restrict__ bias,
                        float* __restrict__ out) {
    // xs: 32 rows x 64 halves (128B/row), XOR swizzle B ^= (row&7)<<4
    // ws: 32 rows x 64 ints  (256B/row), XOR swizzle col ^= (row&3)<<3
    __shared__ __half xs[NBUF][XS_ELEMS];   // 3 x 4KB
    __shared__ int    ws[NBUF][WS_ELEMS];   // 3 x 8KB   -> 36KB static

    const int tid  = threadIdx.x;
    const int lane = tid & 31;
    const int warp = tid >> 5;
    const int mh   = blockIdx.x;            // m-half 0/1 (fast dim: siblings adjacent)
    const int nt   = blockIdx.y;            // n-tile
    const int r    = lane & 3;              // kh sub-row within B fragment
    const int c    = lane >> 2;             // n sub-col within n8 tile
    const int nbase = nt * BN + warp * 16;
    const int col   = nbase + c;
    const int wc    = warp * 16 + c;        // column word index in CTA tile
    const int wcx0 = wc ^ (r << 3);         // swizzled frag columns
    const int wcx1 = (wc + 8) ^ (r << 3);

    // accumulators: [m-subtile 0..1][n-subtile 0..1][frag 0..3]
    float acc[2][2][4];
#pragma unroll
    for (int mi = 0; mi < 2; ++mi)
#pragma unroll
        for (int j = 0; j < 2; ++j)
#pragma unroll
            for (int f = 0; f < 4; ++f) acc[mi][j][f] = 0.0f;

    const int* wsrc = w + (size_t)nt * BN;
    const __half* xsrc = g_xh + (size_t)(mh * BM) * K_DIM;

    // stage copy: x tile (32x64 halves, 4KB) + w tile (32x64 ints, 8KB), one group
    auto copy_stage = [&](int g, int buf) {
#pragma unroll
        for (int i = 0; i < 2; ++i) {           // x: 256 chunks of 16B
            int idx = tid + i * 128;
            int row = idx >> 3;
            int cc  = idx & 7;
            unsigned boff = (unsigned)(row * 128 + cc * 16) ^ (unsigned)((row & 7) << 4);
            const __half* gp = xsrc + (size_t)row * K_DIM + g * BK + cc * 8;
            cp_async16(smem_u32((const char*)&xs[buf][0] + boff), gp);
        }
#pragma unroll
        for (int i = 0; i < 4; ++i) {           // w: 512 chunks of 16B
            int idx = tid + i * 128;
            int row = idx >> 4;
            int cc  = idx & 15;
            int colw = (cc * 4) ^ ((row & 3) << 3);
            const int* gp = wsrc + (size_t)(g * (BK / 2) + row) * N_DIM + cc * 4;
            cp_async16(smem_u32(&ws[buf][row * BN + colw]), gp);
        }
        asm volatile("cp.async.commit_group;\n");
    };

    // fragment read from staged weights: step t covers packed rows t*8 .. t*8+7
    auto lds_w = [&](const int* wsb, int t, unsigned q[4]) {
        const int* p0 = wsb + (t * 8 + r) * BN;
        const int* p1 = p0 + 4 * BN;
        q[0] = (unsigned)p0[wcx0];
        q[1] = (unsigned)p0[wcx1];
        q[2] = (unsigned)p1[wcx0];
        q[3] = (unsigned)p1[wcx1];
    };

    // ldmatrix per-thread terms
    const int row_l = lane & 15;
    const unsigned roff = (unsigned)(row_l * 128);
    const unsigned cb   = (unsigned)((lane >> 4) * 16);
    const unsigned sw   = (unsigned)((row_l & 7) << 4);
    const unsigned xs_base[NBUF] = { smem_u32(&xs[0][0]), smem_u32(&xs[1][0]),
                                     smem_u32(&xs[2][0]) };

    // prologue: 2 stages in flight
    copy_stage(0, 0);
    copy_stage(1, 1);

    float sraw[2];
#pragma unroll
    for (int j = 0; j < 2; ++j)
        sraw[j] = __ldg(scales + col + j * 8);   // group 0

    __half2 s2[2];

    for (int g = 0; g < NSTAGE; ++g) {
        if (g < NSTAGE - 1) asm volatile("cp.async.wait_group 1;\n");
        else                asm volatile("cp.async.wait_group 0;\n");
        __syncthreads();

        // refill pipe (overwrites buffer of stage g-1; safe after the barrier)
        if (g + 2 < NSTAGE) copy_stage(g + 2, (g + 2) % NBUF);

        if ((g & 1) == 0) {
#pragma unroll
            for (int j = 0; j < 2; ++j)
                s2[j] = __half2half2(__float2half_rn(sraw[j]));
            int gq = (g >> 1) + 1;
            if (gq > 63) gq = 63;
#pragma unroll
            for (int j = 0; j < 2; ++j)
                sraw[j] = __ldg(scales + (size_t)gq * N_DIM + col + j * 8);
        }

        const int buf = g % NBUF;
        const unsigned sbase = xs_base[buf];
        const int* wsb = &ws[buf][0];

        unsigned qc[4], qn[4];
        lds_w(wsb, 0, qc);

#pragma unroll
        for (int t = 0; t < 4; ++t) {
            if (t < 3) lds_w(wsb, t + 1, qn);   // prefetch next step's frags

            unsigned a[2][4];
#pragma unroll
            for (int mi = 0; mi < 2; ++mi) {
                unsigned addr = sbase + (unsigned)(mi * 2048) + roff +
                                (((unsigned)(t * 32) + cb) ^ sw);
                ldsm_x4(a[mi][0], a[mi][1], a[mi][2], a[mi][3], addr);
            }

#pragma unroll
            for (int j = 0; j < 2; ++j) {
                unsigned b0 = dequant(qc[j],     s2[j]);
                unsigned b1 = dequant(qc[2 + j], s2[j]);
#pragma unroll
                for (int mi = 0; mi < 2; ++mi)
                    mma_16816(acc[mi][j][0], acc[mi][j][1], acc[mi][j][2], acc[mi][j][3],
                              a[mi][0], a[mi][1], a[mi][2], a[mi][3], b0, b1);
            }
#pragma unroll
            for (int i = 0; i < 4; ++i) qc[i] = qn[i];
        }
    }

    // epilogue: fp32 acc -> fp16 round, + fp16 bias, upcast -> f32 store (final)
#pragma unroll
    for (int mi = 0; mi < 2; ++mi) {
        int m0 = mh * BM + mi * 16 + (lane >> 2);
#pragma unroll
        for (int j = 0; j < 2; ++j) {
            int n = nbase + j * 8 + 2 * (lane & 3);
            float2 bf = *reinterpret_cast<const float2*>(bias + n);
            __half2 bb = __floats2half2_rn(bf.x, bf.y);  // exact

            __half2 v0 = __halves2half2(__float2half_rn(acc[mi][j][0]),
                                        __float2half_rn(acc[mi][j][1]));
            v0 = __hadd2(v0, bb);
            float2 o0 = { __half2float(__low2half(v0)), __half2float(__high2half(v0)) };
            *reinterpret_cast<float2*>(out + (size_t)m0 * N_DIM + n) = o0;

            __half2 v1 = __halves2half2(__float2half_rn(acc[mi][j][2]),
                                        __float2half_rn(acc[mi][j][3]));
            v1 = __hadd2(v1, bb);
            float2 o1 = { __half2float(__low2half(v1)), __half2float(__high2half(v1)) };
            *reinterpret_cast<float2*>(out + (size_t)(m0 + 8) * N_DIM + n) = o1;
        }
    }
}

extern "C" void kernel_launch(void* const* d_in, const int* in_sizes, int n_in,
                              void* d_out, int out_size) {
    const float* x      = (const float*)d_in[0];
    const int*   w      = (const int*)d_in[1];
    const float* scales = (const float*)d_in[2];
    const float* bias   = (const float*)d_in[3];
    float*       out    = (float*)d_out;

    convert_x_kernel<<<(M_DIM * K_DIM / 4 + 255) / 256, 256>>>(x);

    dim3 grid(2, N_DIM / BN);   // (m-half fast) x 448 n-tiles = 896 CTAs, ~6/SM
    int4_linear_kernel<<<grid, 128>>>(w, scales, bias, out);
}

// round 15
// speedup vs baseline: 1.2951x; 1.2951x over previous
#include <cuda_runtime.h>
#include <cuda_fp16.h>
#include <cstdint>
#include <cstddef>

// INT4 packed linear: y[64, 28672] = x[64, 8192] @ dequant(w_packed, scales) + bias
// Harness canonicalizes fp16 tensors to float32 (lossless): x/scales/bias/out are f32.
// Math replicates reference: fp16 dequant ((nib-8)*s in fp16), fp32 MMA accum,
// fp16 rounding of y, fp16 bias add, upcast to f32 for the store.
//
// R15: R10 base (BN=64, M=64, 448 CTAs, NBUF=4 depth-3 cp.async pipeline) +
//      software-pipelined A fragments (LDSM one t-step ahead, like the weight
//      queue) to remove per-step smem-latency stalls; faster x-convert kernel.

#define K_DIM   8192
#define N_DIM   28672
#define M_DIM   64
#define BN      64            // columns per CTA (4 warps x 16 cols)
#define BK      64            // k per stage (32 packed rows); scale-group = 2 stages
#define NSTAGE  (K_DIM / BK)  // 128 stages
#define NBUF    4
#define XS_ELEMS (M_DIM * BK)        // 4096 halves = 8KB per buffer
#define WS_ELEMS ((BK / 2) * BN)     // 2048 ints  = 8KB per buffer
#define SMEM_BYTES (NBUF * (XS_ELEMS * 2 + WS_ELEMS * 4))   // 64KB

// fp16 copy of x (scratch via __device__ global)
__device__ __align__(16) __half g_xh[M_DIM * K_DIM];

__global__ void convert_x_kernel(const float* __restrict__ xf) {
    // 128 blocks x 256 threads x 4 float4 each = 524288 floats = 64*8192
    int base = blockIdx.x * blockDim.x + threadIdx.x;
    const int stride = 128 * 256;
#pragma unroll
    for (int it = 0; it < 4; ++it) {
        int i = (base + it * stride) * 4;
        float4 v = *reinterpret_cast<const float4*>(xf + i);
        *reinterpret_cast<__half2*>(&g_xh[i])     = __floats2half2_rn(v.x, v.y);
        *reinterpret_cast<__half2*>(&g_xh[i + 2]) = __floats2half2_rn(v.z, v.w);
    }
}

__device__ __forceinline__ unsigned smem_u32(const void* p) {
    return (unsigned)__cvta_generic_to_shared(p);
}

__device__ __forceinline__ void ldsm_x4(unsigned& r0, unsigned& r1, unsigned& r2, unsigned& r3,
                                        unsigned addr) {
    asm volatile("ldmatrix.sync.aligned.m8n8.x4.shared.b16 {%0,%1,%2,%3}, [%4];\n"
                 : "=r"(r0), "=r"(r1), "=r"(r2), "=r"(r3)
                 : "r"(addr));
}

__device__ __forceinline__ void mma_16816(float& c0, float& c1, float& c2, float& c3,
                                          unsigned a0, unsigned a1, unsigned a2, unsigned a3,
                                          unsigned b0, unsigned b1) {
    asm volatile("mma.sync.aligned.m16n8k16.row.col.f32.f16.f16.f32 "
                 "{%0,%1,%2,%3}, {%4,%5,%6,%7}, {%8,%9}, {%0,%1,%2,%3};\n"
                 : "+f"(c0), "+f"(c1), "+f"(c2), "+f"(c3)
                 : "r"(a0), "r"(a1), "r"(a2), "r"(a3), "r"(b0), "r"(b1));
}

__device__ __forceinline__ void cp_async16(unsigned saddr, const void* gaddr) {
    asm volatile("cp.async.cg.shared.global [%0], [%1], 16;\n"
                 :: "r"(saddr), "l"(gaddr));
}

// q in [0,256): fp16x2 {1024+lo, 1024+hi} - 1032 (exact), * scale (one fp16 rounding).
__device__ __forceinline__ unsigned dequant(unsigned q, __half2 s2) {
    unsigned t = ((q | (q << 12)) | 0x64006400u) & 0x640F640Fu;
    __half2 th = *reinterpret_cast<__half2*>(&t);
    const unsigned offc = 0x64086408u;  // half2 {1032, 1032}
    __half2 off = *reinterpret_cast<const __half2*>(&offc);
    __half2 wv = __hmul2(__hsub2(th, off), s2);
    return *reinterpret_cast<unsigned*>(&wv);
}

__global__ __launch_bounds__(128, 3)
void int4_linear_kernel(const int* __restrict__ w,
                        const float* __restrict__ scales,
                        const float* __restrict__ bias,
                        float* __restrict__ out) {
    // Dynamic SMEM: NBUF x { x tile 64x64 halves (swizzle B^=(row&7)<<4),
    //                        w tile 32x64 ints   (swizzle col^=(row&3)<<3) }
    extern __shared__ __align__(16) char smem_raw[];
    __half* xs_all = (__half*)smem_raw;                        // NBUF * 4096 halves
    int*    ws_all = (int*)(smem_raw + NBUF * XS_ELEMS * 2);   // NBUF * 2048 ints

    const int tid  = threadIdx.x;
    const int lane = tid & 31;
    const int warp = tid >> 5;
    const int r    = lane & 3;    // kh sub-row within B fragment
    const int c    = lane >> 2;   // n sub-col within n8 tile
    const int nwarp = blockIdx.x * BN + warp * 16;
    const int col   = nwarp + c;
    const int wc    = warp * 16 + c;                 // column word index in CTA tile
    const int wcx0 = wc ^ (r << 3);                  // swizzled frag columns
    const int wcx1 = (wc + 8) ^ (r << 3);

    float acc[4][2][4];
#pragma unroll
    for (int mi = 0; mi < 4; ++mi)
#pragma unroll
        for (int j = 0; j < 2; ++j)
#pragma unroll
            for (int f = 0; f < 4; ++f) acc[mi][j][f] = 0.0f;

    const int* wsrc = w + (size_t)blockIdx.x * BN;

    // stage copy: x tile (64x64 halves) + w tile (32x64 ints), one commit group
    auto copy_stage = [&](int g, int buf) {
        __half* xsb = xs_all + buf * XS_ELEMS;
        int*    wsb = ws_all + buf * WS_ELEMS;
#pragma unroll
        for (int i = 0; i < 4; ++i) {           // x: 512 chunks of 16B
            int idx = tid + i * 128;
            int row = idx >> 3;
            int cc  = idx & 7;
            unsigned boff = (unsigned)(row * 128 + cc * 16) ^ (unsigned)((row & 7) << 4);
            const __half* gp = g_xh + (size_t)row * K_DIM + (size_t)g * BK + cc * 8;
            cp_async16(smem_u32((const char*)xsb + boff), gp);
        }
#pragma unroll
        for (int i = 0; i < 4; ++i) {           // w: 512 chunks of 16B
            int idx = tid + i * 128;
            int row = idx >> 4;
            int cc  = idx & 15;
            int colw = (cc * 4) ^ ((row & 3) << 3);
            const int* gp = wsrc + (size_t)(g * (BK / 2) + row) * N_DIM + cc * 4;
            cp_async16(smem_u32(&wsb[row * BN + colw]), gp);
        }
        asm volatile("cp.async.commit_group;\n");
    };

    // fragment read from staged weights: step t covers packed rows t*8 .. t*8+7
    auto lds_w = [&](const int* wsb, int t, unsigned q[4]) {
        const int* p0 = wsb + (t * 8 + r) * BN;
        const int* p1 = p0 + 4 * BN;
        q[0] = (unsigned)p0[wcx0];
        q[1] = (unsigned)p0[wcx1];
        q[2] = (unsigned)p1[wcx0];
        q[3] = (unsigned)p1[wcx1];
    };

    // ldmatrix per-thread terms
    const int row_l = lane & 15;
    const unsigned roff = (unsigned)(row_l * 128);
    const unsigned cb   = (unsigned)((lane >> 4) * 16);
    const unsigned sw   = (unsigned)((row_l & 7) << 4);
    unsigned xs_base[NBUF];
#pragma unroll
    for (int i = 0; i < NBUF; ++i) xs_base[i] = smem_u32(xs_all + i * XS_ELEMS);

    // A-fragment loader: all 4 m16 tiles for one t-step
    auto ldsm_step = [&](unsigned sbase, int t, unsigned a[4][4]) {
#pragma unroll
        for (int mi = 0; mi < 4; ++mi) {
            unsigned addr = sbase + (unsigned)(mi * 2048) + roff +
                            (((unsigned)(t * 32) + cb) ^ sw);
            ldsm_x4(a[mi][0], a[mi][1], a[mi][2], a[mi][3], addr);
        }
    };

    // prologue: 3 stages in flight
    copy_stage(0, 0);
    copy_stage(1, 1);
    copy_stage(2, 2);

    float sraw[2];
#pragma unroll
    for (int j = 0; j < 2; ++j)
        sraw[j] = __ldg(scales + col + j * 8);   // group 0

    __half2 s2[2];

    for (int g = 0; g < NSTAGE; ++g) {
        // ensure stage g's group has landed (exact tail handling)
        if (g < NSTAGE - 2)       asm volatile("cp.async.wait_group 2;\n");
        else if (g == NSTAGE - 2) asm volatile("cp.async.wait_group 1;\n");
        else                      asm volatile("cp.async.wait_group 0;\n");
        __syncthreads();

        // refill pipe (overwrites buffer of stage g-1; safe after the barrier)
        if (g + 3 < NSTAGE) copy_stage(g + 3, (g + 3) % NBUF);

        if ((g & 1) == 0) {
#pragma unroll
            for (int j = 0; j < 2; ++j)
                s2[j] = __half2half2(__float2half_rn(sraw[j]));
            int gn = (g >> 1) + 1;
            if (gn > 63) gn = 63;
#pragma unroll
            for (int j = 0; j < 2; ++j)
                sraw[j] = __ldg(scales + (size_t)gn * N_DIM + col + j * 8);
        }

        const int buf = g % NBUF;
        const unsigned sbase = xs_base[buf];
        const int* wsb = ws_all + buf * WS_ELEMS;

        // step-0 operands (only exposed smem latency in the stage)
        unsigned qc[4], qn[4];
        unsigned a_cur[4][4], a_nxt[4][4];
        lds_w(wsb, 0, qc);
        ldsm_step(sbase, 0, a_cur);

#pragma unroll
        for (int t = 0; t < 4; ++t) {
            if (t < 3) {
                lds_w(wsb, t + 1, qn);           // next step's weight frags
                ldsm_step(sbase, t + 1, a_nxt);  // next step's A frags
            }

#pragma unroll
            for (int j = 0; j < 2; ++j) {
                unsigned b0 = dequant(qc[j],     s2[j]);
                unsigned b1 = dequant(qc[2 + j], s2[j]);
#pragma unroll
                for (int mi = 0; mi < 4; ++mi)
                    mma_16816(acc[mi][j][0], acc[mi][j][1], acc[mi][j][2], acc[mi][j][3],
                              a_cur[mi][0], a_cur[mi][1], a_cur[mi][2], a_cur[mi][3],
                              b0, b1);
            }

#pragma unroll
            for (int i = 0; i < 4; ++i) qc[i] = qn[i];
#pragma unroll
            for (int mi = 0; mi < 4; ++mi)
#pragma unroll
                for (int f = 0; f < 4; ++f) a_cur[mi][f] = a_nxt[mi][f];
        }
    }

    // epilogue: fp32 acc -> fp16 round, + fp16 bias, upcast -> f32 store
#pragma unroll
    for (int mi = 0; mi < 4; ++mi) {
        int m0 = mi * 16 + (lane >> 2);
#pragma unroll
        for (int j = 0; j < 2; ++j) {
            int n = nwarp + j * 8 + 2 * (lane & 3);
            float2 bf = *reinterpret_cast<const float2*>(bias + n);
            __half2 bb = __floats2half2_rn(bf.x, bf.y);  // exact

            __half2 v0 = __halves2half2(__float2half_rn(acc[mi][j][0]),
                                        __float2half_rn(acc[mi][j][1]));
            v0 = __hadd2(v0, bb);
            float2 o0 = { __half2float(__low2half(v0)), __half2float(__high2half(v0)) };
            *reinterpret_cast<float2*>(out + (size_t)m0 * N_DIM + n) = o0;

            __half2 v1 = __halves2half2(__float2half_rn(acc[mi][j][2]),
                                        __float2half_rn(acc[mi][j][3]));
            v1 = __hadd2(v1, bb);
            float2 o1 = { __half2float(__low2half(v1)), __half2float(__high2half(v1)) };
            *reinterpret_cast<float2*>(out + (size_t)(m0 + 8) * N_DIM + n) = o1;
        }
    }
}

extern "C" void kernel_launch(void* const* d_in, const int* in_sizes, int n_in,
                              void* d_out, int out_size) {
    const float* x      = (const float*)d_in[0];
    const int*   w      = (const int*)d_in[1];
    const float* scales = (const float*)d_in[2];
    const float* bias   = (const float*)d_in[3];
    float*       out    = (float*)d_out;

    cudaFuncSetAttribute(int4_linear_kernel,
                         cudaFuncAttributeMaxDynamicSharedMemorySize, SMEM_BYTES);

    convert_x_kernel<<<128, 256>>>(x);

    dim3 grid(N_DIM / BN);   // 448 CTAs (~3 per SM, balanced)
    int4_linear_kernel<<<grid, 128, SMEM_BYTES>>>(w, scales, bias, out);
}